// round 3
// baseline (speedup 1.0000x reference)
#include <cuda_runtime.h>
#include <cuda_bf16.h>
#include <cstdint>
#include <math.h>

#define BB 4
#define SS 4096
#define DD 4096
#define CC 256
#define NROW (BB*SS)   // 16384 token rows

// ---------------- scratch (device globals; no allocations allowed) ----------
__device__ float         g_H [(size_t)NROW * CC];   // down-proj result fp32
__device__ __nv_bfloat16 g_G [(size_t)NROW * CC];   // gelu(conv(H)) bf16
__device__ __nv_bfloat16 g_wd[(size_t)CC * DD];     // gamma-scaled w_down bf16
__device__ __nv_bfloat16 g_wu[(size_t)DD * CC];     // w_up bf16
__device__ float         g_wc[3][CC];               // transposed conv weights
__device__ float         g_gate[NROW];              // per-token sigmoid gate
__device__ float         g_u[CC];                   // sum_d gamma*wd
__device__ float         g_v[CC];                   // sum_d beta*wd

// ---------------- helpers -----------------------------------------------------
__device__ __forceinline__ void cp16(void* dst_smem, const void* src_gmem) {
    uint32_t d = (uint32_t)__cvta_generic_to_shared(dst_smem);
    asm volatile("cp.async.cg.shared.global [%0], [%1], 16;\n" :: "r"(d), "l"(src_gmem));
}
__device__ __forceinline__ void cp_commit() { asm volatile("cp.async.commit_group;\n"); }

__device__ __forceinline__ float gelu_exact(float v) {
    return 0.5f * v * (1.0f + erff(v * 0.70710678118654752f));
}

// ---------------- kernel 0a: weight conversion (W' = gamma .* w_down) --------
__global__ void k_cvt(const float* __restrict__ wd, const float* __restrict__ wu,
                      const float* __restrict__ wc, const float* __restrict__ gamma) {
    int i = blockIdx.x * blockDim.x + threadIdx.x;
    if (i < CC * DD) {
        g_wd[i] = __float2bfloat16(wd[i] * gamma[i & (DD - 1)]);
        g_wu[i] = __float2bfloat16(wu[i]);
    }
    if (i < CC * 3) g_wc[i % 3][i / 3] = wc[i];
}

// ---------------- kernel 0b: u[c], v[c] reductions ----------------------------
__global__ __launch_bounds__(256) void k_uv(const float* __restrict__ wd,
                                            const float* __restrict__ gamma,
                                            const float* __restrict__ beta) {
    int warp = threadIdx.x >> 5, lane = threadIdx.x & 31;
    int c = blockIdx.x * 8 + warp;
    const float* row = wd + (size_t)c * DD;
    float su = 0.f, sv = 0.f;
    for (int d = lane; d < DD; d += 32) {
        float w = row[d];
        su += gamma[d] * w;
        sv += beta[d] * w;
    }
#pragma unroll
    for (int off = 16; off; off >>= 1) {
        su += __shfl_down_sync(0xffffffffu, su, off);
        sv += __shfl_down_sync(0xffffffffu, sv, off);
    }
    if (lane == 0) { g_u[c] = su; g_v[c] = sv; }
}

// ---------------- GEMM1: fused LN + down-proj + gate --------------------------
// C-tile 128x128, K=4096, BK=32, 3-stage. A = raw x (fp32 -> bf16 on the fly),
// B = g_wd (gamma-scaled w_down). Row stats (mu, var, gate-dot) accumulated
// during A loads; LN correction + gate applied in epilogue.
#define G1_STG_BYTES 20480           // A 128x40x2 + B 128x40x2
#define G1_SMEM (3 * G1_STG_BYTES)

__global__ __launch_bounds__(256, 1) void gemm1(const float* __restrict__ x,
                                                const float* __restrict__ wg,
                                                const float* __restrict__ b_gate) {
    extern __shared__ char dsm[];
    __shared__ float s_rstd[128];
    __shared__ float s_rmu[128];     // rstd * mu

    int t = threadIdx.x;
    int lane = t & 31, warp = t >> 5;
    int wm = warp >> 2, wn = warp & 3;
    int m_base = blockIdx.y * 128;
    const __nv_bfloat16* Bblk = g_wd + (size_t)blockIdx.x * 128 * DD;

    float acc[4][4][4];
#pragma unroll
    for (int i = 0; i < 4; i++)
#pragma unroll
        for (int j = 0; j < 4; j++)
#pragma unroll
            for (int k = 0; k < 4; k++) acc[i][j][k] = 0.f;

    float st_s[4], st_ss[4], st_gd[4];
#pragma unroll
    for (int i = 0; i < 4; i++) { st_s[i] = 0.f; st_ss[i] = 0.f; st_gd[i] = 0.f; }

    float4 Ar[4];

    auto lda = [&](int kt) {
        int k0 = kt * 32;
#pragma unroll
        for (int i = 0; i < 4; i++) {
            int ch = t + i * 256;
            int row = ch >> 3, c4 = ch & 7;
            float4 a = *(const float4*)&x[(size_t)(m_base + row) * DD + k0 + c4 * 4];
            float4 w = *(const float4*)&wg[k0 + c4 * 4];
            Ar[i] = a;
            st_s[i]  += a.x + a.y + a.z + a.w;
            st_ss[i] += a.x * a.x + a.y * a.y + a.z * a.z + a.w * a.w;
            st_gd[i] += a.x * w.x + a.y * w.y + a.z * w.z + a.w * w.w;
        }
    };
    auto sta = [&](int st) {
        char* sa = dsm + st * G1_STG_BYTES;
#pragma unroll
        for (int i = 0; i < 4; i++) {
            int ch = t + i * 256;
            int row = ch >> 3, c4 = ch & 7;
            __nv_bfloat162 lo = __floats2bfloat162_rn(Ar[i].x, Ar[i].y);
            __nv_bfloat162 hi = __floats2bfloat162_rn(Ar[i].z, Ar[i].w);
            uint2 p;
            p.x = *(uint32_t*)&lo;
            p.y = *(uint32_t*)&hi;
            *(uint2*)(sa + row * 80 + c4 * 8) = p;
        }
    };
    auto ldb = [&](int st, int kt) {
        int k0 = kt * 32;
        char* sb = dsm + st * G1_STG_BYTES + 10240;
#pragma unroll
        for (int i = 0; i < 2; i++) {
            int ch = t + i * 256;
            int r = ch >> 2, c = ch & 3;
            cp16(sb + r * 80 + c * 16, Bblk + (size_t)r * DD + k0 + c * 8);
        }
        cp_commit();
    };

    const int NK = DD / 32;          // 128
    // prologue: stages 0,1 in smem; stage 2 staged in registers
    lda(0); sta(0); ldb(0, 0);
    lda(1); sta(1); ldb(1, 1);
    lda(2);

    for (int kt = 0; kt < NK; kt++) {
        if (kt + 1 < NK) asm volatile("cp.async.wait_group 1;\n" ::: "memory");
        else             asm volatile("cp.async.wait_group 0;\n" ::: "memory");
        __syncthreads();

        if (kt + 2 < NK) {
            int st = (kt + 2) % 3;
            sta(st);
            ldb(st, kt + 2);
            if (kt + 3 < NK) lda(kt + 3);
        }

        char* sa = dsm + (kt % 3) * G1_STG_BYTES;
        char* sb = sa + 10240;
#pragma unroll
        for (int kk = 0; kk < 32; kk += 16) {
            uint32_t a[4][4];
#pragma unroll
            for (int im = 0; im < 4; im++) {
                uint32_t addr = (uint32_t)__cvta_generic_to_shared(
                    sa + (wm * 64 + im * 16 + (lane & 15)) * 80 + (kk + ((lane >> 4) << 3)) * 2);
                asm volatile("ldmatrix.sync.aligned.m8n8.x4.shared.b16 {%0,%1,%2,%3}, [%4];\n"
                             : "=r"(a[im][0]), "=r"(a[im][1]), "=r"(a[im][2]), "=r"(a[im][3])
                             : "r"(addr));
            }
            uint32_t b[4][2];
#pragma unroll
            for (int in_ = 0; in_ < 4; in_++) {
                uint32_t addr = (uint32_t)__cvta_generic_to_shared(
                    sb + (wn * 32 + in_ * 8 + (lane & 7)) * 80 + (kk + (((lane >> 3) & 1) << 3)) * 2);
                asm volatile("ldmatrix.sync.aligned.m8n8.x2.shared.b16 {%0,%1}, [%2];\n"
                             : "=r"(b[in_][0]), "=r"(b[in_][1])
                             : "r"(addr));
            }
#pragma unroll
            for (int im = 0; im < 4; im++)
#pragma unroll
                for (int in_ = 0; in_ < 4; in_++)
                    asm volatile(
                        "mma.sync.aligned.m16n8k16.row.col.f32.bf16.bf16.f32 "
                        "{%0,%1,%2,%3}, {%4,%5,%6,%7}, {%8,%9}, {%0,%1,%2,%3};\n"
                        : "+f"(acc[im][in_][0]), "+f"(acc[im][in_][1]),
                          "+f"(acc[im][in_][2]), "+f"(acc[im][in_][3])
                        : "r"(a[im][0]), "r"(a[im][1]), "r"(a[im][2]), "r"(a[im][3]),
                          "r"(b[in_][0]), "r"(b[in_][1]));
        }
        __syncthreads();
    }

    // --- row stats: reduce across the 8 lanes sharing each row ---------------
#pragma unroll
    for (int i = 0; i < 4; i++) {
#pragma unroll
        for (int off = 4; off; off >>= 1) {
            st_s[i]  += __shfl_down_sync(0xffffffffu, st_s[i],  off, 8);
            st_ss[i] += __shfl_down_sync(0xffffffffu, st_ss[i], off, 8);
            st_gd[i] += __shfl_down_sync(0xffffffffu, st_gd[i], off, 8);
        }
    }
    if ((t & 7) == 0) {
        float bg = b_gate[0];
#pragma unroll
        for (int i = 0; i < 4; i++) {
            int row = (t >> 3) + 32 * i;
            float mu = st_s[i] * (1.0f / DD);
            float var = st_ss[i] * (1.0f / DD) - mu * mu;
            float rstd = rsqrtf(var + 1e-5f);
            s_rstd[row] = rstd;
            s_rmu[row] = rstd * mu;
            g_gate[m_base + row] = 1.0f / (1.0f + expf(-(st_gd[i] + bg)));
        }
    }
    __syncthreads();

    // --- epilogue: h = rstd*acc - rstd*mu*u[c] + v[c] -------------------------
    int r = lane >> 2;
    int cp2 = (lane & 3) * 2;
#pragma unroll
    for (int im = 0; im < 4; im++) {
        int ml0 = wm * 64 + im * 16 + r;
        int ml1 = ml0 + 8;
        float rs0 = s_rstd[ml0], rm0 = s_rmu[ml0];
        float rs1 = s_rstd[ml1], rm1 = s_rmu[ml1];
#pragma unroll
        for (int in_ = 0; in_ < 4; in_++) {
            int c = blockIdx.x * 128 + wn * 32 + in_ * 8 + cp2;
            float u0 = g_u[c], u1 = g_u[c + 1];
            float v0 = g_v[c], v1 = g_v[c + 1];
            float2 o0 = make_float2(rs0 * acc[im][in_][0] - rm0 * u0 + v0,
                                    rs0 * acc[im][in_][1] - rm0 * u1 + v1);
            float2 o1 = make_float2(rs1 * acc[im][in_][2] - rm1 * u0 + v0,
                                    rs1 * acc[im][in_][3] - rm1 * u1 + v1);
            *(float2*)&g_H[(size_t)(m_base + ml0) * CC + c] = o0;
            *(float2*)&g_H[(size_t)(m_base + ml1) * CC + c] = o1;
        }
    }
}

// ---------------- GEMM2: up-proj + gate/residual epilogue (round-1 proven) ---
template <int N_TOTAL, int K_TOTAL>
__global__ __launch_bounds__(256, 2) void gemm2(const float* __restrict__ x,
                                                float* __restrict__ out) {
    __shared__ __nv_bfloat16 sA[2][128][40];
    __shared__ __nv_bfloat16 sB[2][128][40];

    const __nv_bfloat16* A = g_G;
    const __nv_bfloat16* B = g_wu;

    int t = threadIdx.x;
    int lane = t & 31, warp = t >> 5;
    int wm = warp >> 2, wn = warp & 3;

    const __nv_bfloat16* Ablk = A + (size_t)blockIdx.y * 128 * K_TOTAL;
    const __nv_bfloat16* Bblk = B + (size_t)blockIdx.x * 128 * K_TOTAL;

    float acc[4][4][4];
#pragma unroll
    for (int i = 0; i < 4; i++)
#pragma unroll
        for (int j = 0; j < 4; j++)
#pragma unroll
            for (int k = 0; k < 4; k++) acc[i][j][k] = 0.f;

    auto load_stage = [&](int st, int kt) {
        int k0 = kt * 32;
#pragma unroll
        for (int j = 0; j < 2; j++) {
            int ch = t + j * 256;
            int row = ch >> 2;
            int kc = ch & 3;
            cp16(&sA[st][row][kc * 8], Ablk + (size_t)row * K_TOTAL + k0 + kc * 8);
            cp16(&sB[st][row][kc * 8], Bblk + (size_t)row * K_TOTAL + k0 + kc * 8);
        }
    };

    const int nk = K_TOTAL / 32;
    load_stage(0, 0);
    cp_commit();

    for (int kt = 0; kt < nk; ++kt) {
        if (kt + 1 < nk) {
            load_stage((kt + 1) & 1, kt + 1);
            cp_commit();
            asm volatile("cp.async.wait_group 1;\n" ::: "memory");
        } else {
            asm volatile("cp.async.wait_group 0;\n" ::: "memory");
        }
        __syncthreads();

        int st = kt & 1;
#pragma unroll
        for (int kk = 0; kk < 32; kk += 16) {
            uint32_t a[4][4];
#pragma unroll
            for (int im = 0; im < 4; im++) {
                uint32_t addr = (uint32_t)__cvta_generic_to_shared(
                    &sA[st][wm * 64 + im * 16 + (lane & 15)][kk + ((lane >> 4) << 3)]);
                asm volatile("ldmatrix.sync.aligned.m8n8.x4.shared.b16 {%0,%1,%2,%3}, [%4];\n"
                             : "=r"(a[im][0]), "=r"(a[im][1]), "=r"(a[im][2]), "=r"(a[im][3])
                             : "r"(addr));
            }
            uint32_t b[4][2];
#pragma unroll
            for (int in_ = 0; in_ < 4; in_++) {
                uint32_t addr = (uint32_t)__cvta_generic_to_shared(
                    &sB[st][wn * 32 + in_ * 8 + (lane & 7)][kk + (((lane >> 3) & 1) << 3)]);
                asm volatile("ldmatrix.sync.aligned.m8n8.x2.shared.b16 {%0,%1}, [%2];\n"
                             : "=r"(b[in_][0]), "=r"(b[in_][1])
                             : "r"(addr));
            }
#pragma unroll
            for (int im = 0; im < 4; im++)
#pragma unroll
                for (int in_ = 0; in_ < 4; in_++)
                    asm volatile(
                        "mma.sync.aligned.m16n8k16.row.col.f32.bf16.bf16.f32 "
                        "{%0,%1,%2,%3}, {%4,%5,%6,%7}, {%8,%9}, {%0,%1,%2,%3};\n"
                        : "+f"(acc[im][in_][0]), "+f"(acc[im][in_][1]),
                          "+f"(acc[im][in_][2]), "+f"(acc[im][in_][3])
                        : "r"(a[im][0]), "r"(a[im][1]), "r"(a[im][2]), "r"(a[im][3]),
                          "r"(b[in_][0]), "r"(b[in_][1]));
        }
        __syncthreads();
    }

    int r = lane >> 2;
    int cp2 = (lane & 3) * 2;
    int m_base = blockIdx.y * 128 + wm * 64;
    int n_base = blockIdx.x * 128 + wn * 32;

#pragma unroll
    for (int im = 0; im < 4; im++) {
        int m = m_base + im * 16 + r;
        float gA = g_gate[m];
        float gB = g_gate[m + 8];
#pragma unroll
        for (int in_ = 0; in_ < 4; in_++) {
            int n = n_base + in_ * 8 + cp2;
            float2 xv0 = *(const float2*)&x[(size_t)m * DD + n];
            float2 xv1 = *(const float2*)&x[(size_t)(m + 8) * DD + n];
            float2 o0 = make_float2(xv0.x + gA * acc[im][in_][0],
                                    xv0.y + gA * acc[im][in_][1]);
            float2 o1 = make_float2(xv1.x + gB * acc[im][in_][2],
                                    xv1.y + gB * acc[im][in_][3]);
            *(float2*)&out[(size_t)m * DD + n] = o0;
            *(float2*)&out[(size_t)(m + 8) * DD + n] = o1;
        }
    }
}

// ---------------- kernel 3: depthwise conv(k=3) + exact GELU -> bf16 ---------
__global__ __launch_bounds__(256) void k_conv() {
    int t = threadIdx.x;
    int row = blockIdx.x * 4 + (t >> 6);
    int c4 = t & 63;
    int s = row & (SS - 1);

    const float4* Hc = ((const float4*)g_H) + (size_t)row * (CC / 4);
    float4 z = make_float4(0.f, 0.f, 0.f, 0.f);
    float4 hm = (s > 0)      ? Hc[c4 - (CC / 4)] : z;
    float4 hc = Hc[c4];
    float4 hp = (s < SS - 1) ? Hc[c4 + (CC / 4)] : z;

    float4 w0 = ((const float4*)g_wc[0])[c4];
    float4 w1 = ((const float4*)g_wc[1])[c4];
    float4 w2 = ((const float4*)g_wc[2])[c4];

    float vx = gelu_exact(hm.x * w0.x + hc.x * w1.x + hp.x * w2.x);
    float vy = gelu_exact(hm.y * w0.y + hc.y * w1.y + hp.y * w2.y);
    float vz = gelu_exact(hm.z * w0.z + hc.z * w1.z + hp.z * w2.z);
    float vw = gelu_exact(hm.w * w0.w + hc.w * w1.w + hp.w * w2.w);

    __nv_bfloat162* G2 = ((__nv_bfloat162*)g_G) + (size_t)row * (CC / 2);
    G2[c4 * 2 + 0] = __floats2bfloat162_rn(vx, vy);
    G2[c4 * 2 + 1] = __floats2bfloat162_rn(vz, vw);
}

// ---------------- launch ------------------------------------------------------
extern "C" void kernel_launch(void* const* d_in, const int* in_sizes, int n_in,
                              void* d_out, int out_size) {
    const float* x      = (const float*)d_in[0];
    const float* gamma  = (const float*)d_in[1];
    const float* beta   = (const float*)d_in[2];
    const float* w_down = (const float*)d_in[3];
    const float* w_conv = (const float*)d_in[4];
    const float* w_up   = (const float*)d_in[5];
    const float* w_gate = (const float*)d_in[6];
    const float* b_gate = (const float*)d_in[7];
    float* out = (float*)d_out;

    cudaFuncSetAttribute(gemm1, cudaFuncAttributeMaxDynamicSharedMemorySize, G1_SMEM);

    k_cvt<<<4096, 256>>>(w_down, w_up, w_conv, gamma);
    k_uv<<<32, 256>>>(w_down, gamma, beta);
    gemm1<<<dim3(2, NROW / 128), 256, G1_SMEM>>>(x, w_gate, b_gate);
    k_conv<<<NROW / 4, 256>>>();
    gemm2<DD, CC><<<dim3(DD / 128, NROW / 128), 256>>>(x, out);
}

// round 4
// speedup vs baseline: 1.4958x; 1.4958x over previous
#include <cuda_runtime.h>
#include <cuda_bf16.h>
#include <cstdint>
#include <math.h>

#define BB 4
#define SS 4096
#define DD 4096
#define CC 256
#define NROW (BB*SS)   // 16384 token rows

// ---------------- scratch (device globals; no allocations allowed) ----------
__device__ __nv_bfloat16 g_xn[(size_t)NROW * DD];   // normalized x, bf16
__device__ float         g_H [(size_t)NROW * CC];   // down-proj result fp32
__device__ __nv_bfloat16 g_G [(size_t)NROW * CC];   // gelu(conv(H)) bf16
__device__ __nv_bfloat16 g_wd[(size_t)CC * DD];     // w_down bf16
__device__ __nv_bfloat16 g_wu[(size_t)DD * CC];     // w_up bf16
__device__ float         g_wc[3][CC];               // transposed conv weights
__device__ float         g_gate[NROW];              // per-token sigmoid gate

// ---------------- helpers -----------------------------------------------------
__device__ __forceinline__ void cp16(void* dst_smem, const void* src_gmem) {
    uint32_t d = (uint32_t)__cvta_generic_to_shared(dst_smem);
    asm volatile("cp.async.cg.shared.global [%0], [%1], 16;\n" :: "r"(d), "l"(src_gmem));
}
__device__ __forceinline__ void cp_commit() { asm volatile("cp.async.commit_group;\n"); }

__device__ __forceinline__ float gelu_exact(float v) {
    return 0.5f * v * (1.0f + erff(v * 0.70710678118654752f));
}

// ---------------- kernel 0: weight conversion --------------------------------
__global__ void k_cvt(const float* __restrict__ wd, const float* __restrict__ wu,
                      const float* __restrict__ wc) {
    int i = blockIdx.x * blockDim.x + threadIdx.x;
    if (i < CC * DD) {
        g_wd[i] = __float2bfloat16(wd[i]);
        g_wu[i] = __float2bfloat16(wu[i]);
    }
    if (i < CC * 3) g_wc[i % 3][i / 3] = wc[i];
}

// ---------------- kernel 1: LN stats + gate + write xn (bf16) ----------------
__global__ __launch_bounds__(256) void k_ln(const float4* __restrict__ x,
                                            const float* __restrict__ gamma,
                                            const float* __restrict__ beta,
                                            const float4* __restrict__ wg,
                                            const float* __restrict__ b_gate) {
    int row = blockIdx.x;
    int t = threadIdx.x;
    const float4* xr = x + (size_t)row * (DD / 4);

    float4 v[4];
    float s = 0.f, ss = 0.f, gd = 0.f;
#pragma unroll
    for (int i = 0; i < 4; i++) {
        int idx = t + i * 256;
        float4 a = xr[idx];
        v[i] = a;
        float4 w = wg[idx];
        s  += a.x + a.y + a.z + a.w;
        ss += a.x * a.x + a.y * a.y + a.z * a.z + a.w * a.w;
        gd += a.x * w.x + a.y * w.y + a.z * w.z + a.w * w.w;
    }

    __shared__ float red[3][8];
    int lane = t & 31, warp = t >> 5;
#pragma unroll
    for (int off = 16; off; off >>= 1) {
        s  += __shfl_down_sync(0xffffffffu, s,  off);
        ss += __shfl_down_sync(0xffffffffu, ss, off);
        gd += __shfl_down_sync(0xffffffffu, gd, off);
    }
    if (lane == 0) { red[0][warp] = s; red[1][warp] = ss; red[2][warp] = gd; }
    __syncthreads();
    if (warp == 0) {
        s  = (lane < 8) ? red[0][lane] : 0.f;
        ss = (lane < 8) ? red[1][lane] : 0.f;
        gd = (lane < 8) ? red[2][lane] : 0.f;
#pragma unroll
        for (int off = 4; off; off >>= 1) {
            s  += __shfl_down_sync(0xffffffffu, s,  off);
            ss += __shfl_down_sync(0xffffffffu, ss, off);
            gd += __shfl_down_sync(0xffffffffu, gd, off);
        }
        if (lane == 0) { red[0][0] = s; red[1][0] = ss; red[2][0] = gd; }
    }
    __syncthreads();
    s = red[0][0]; ss = red[1][0]; gd = red[2][0];

    const float inv_d = 1.0f / (float)DD;
    float mu = s * inv_d;
    float var = ss * inv_d - mu * mu;
    float rstd = rsqrtf(var + 1e-5f);

    if (t == 0) {
        float z = gd + b_gate[0];
        g_gate[row] = 1.0f / (1.0f + expf(-z));
    }

    __nv_bfloat162* outr = ((__nv_bfloat162*)g_xn) + (size_t)row * (DD / 2);
    const float4* g4p = (const float4*)gamma;
    const float4* b4p = (const float4*)beta;
#pragma unroll
    for (int i = 0; i < 4; i++) {
        int idx = t + i * 256;
        float4 a = v[i];
        float4 g4 = g4p[idx];
        float4 b4 = b4p[idx];
        float nx = (a.x - mu) * rstd * g4.x + b4.x;
        float ny = (a.y - mu) * rstd * g4.y + b4.y;
        float nz = (a.z - mu) * rstd * g4.z + b4.z;
        float nw = (a.w - mu) * rstd * g4.w + b4.w;
        outr[idx * 2 + 0] = __floats2bfloat162_rn(nx, ny);
        outr[idx * 2 + 1] = __floats2bfloat162_rn(nz, nw);
    }
}

// ---------------- GEMM: C[M,N] = A[M,K] * B[N,K]^T, 3-stage cp.async ---------
// BM=128, BN=128, BK=32, 256 threads (8 warps = 2x4), warp tile 64x32.
// EPI==0: write fp32 to g_H. A = g_xn, B = g_wd.
// EPI==1: out = x + gate * acc. A = g_G, B = g_wu.
#define STG 20480                       // bytes per stage: A 128x80 + B 128x80
#define GEMM_SMEM (3 * STG)

template <int N_TOTAL, int K_TOTAL, int EPI>
__global__ __launch_bounds__(256, 2) void gemm_bf16(const float* __restrict__ x,
                                                    float* __restrict__ out) {
    extern __shared__ char dsm[];

    const __nv_bfloat16* A = (EPI == 0) ? g_xn : g_G;
    const __nv_bfloat16* B = (EPI == 0) ? g_wd : g_wu;

    int t = threadIdx.x;
    int lane = t & 31, warp = t >> 5;
    int wm = warp >> 2;      // 0..1
    int wn = warp & 3;       // 0..3

    const __nv_bfloat16* Ablk = A + (size_t)blockIdx.y * 128 * K_TOTAL;
    const __nv_bfloat16* Bblk = B + (size_t)blockIdx.x * 128 * K_TOTAL;

    float acc[4][4][4];
#pragma unroll
    for (int i = 0; i < 4; i++)
#pragma unroll
        for (int j = 0; j < 4; j++)
#pragma unroll
            for (int k = 0; k < 4; k++) acc[i][j][k] = 0.f;

    auto load_stage = [&](int st, int kt) {
        int k0 = kt * 32;
        char* sa = dsm + st * STG;
        char* sb = sa + 10240;
#pragma unroll
        for (int j = 0; j < 2; j++) {
            int ch = t + j * 256;          // 0..511
            int row = ch >> 2;
            int kc = ch & 3;
            cp16(sa + row * 80 + kc * 16, Ablk + (size_t)row * K_TOTAL + k0 + kc * 8);
            cp16(sb + row * 80 + kc * 16, Bblk + (size_t)row * K_TOTAL + k0 + kc * 8);
        }
        cp_commit();
    };

    const int nk = K_TOTAL / 32;
    load_stage(0, 0);
    load_stage(1, 1);

    for (int kt = 0; kt < nk; ++kt) {
        // issue prefetch for kt+2 BEFORE waiting on kt: ~2-iteration distance
        if (kt + 2 < nk) {
            load_stage((kt + 2) % 3, kt + 2);
            asm volatile("cp.async.wait_group 2;\n" ::: "memory");
        } else if (kt + 1 < nk) {
            asm volatile("cp.async.wait_group 1;\n" ::: "memory");
        } else {
            asm volatile("cp.async.wait_group 0;\n" ::: "memory");
        }
        __syncthreads();

        char* sa = dsm + (kt % 3) * STG;
        char* sb = sa + 10240;
#pragma unroll
        for (int kk = 0; kk < 32; kk += 16) {
            uint32_t a[4][4];
#pragma unroll
            for (int im = 0; im < 4; im++) {
                uint32_t addr = (uint32_t)__cvta_generic_to_shared(
                    sa + (wm * 64 + im * 16 + (lane & 15)) * 80 + (kk + ((lane >> 4) << 3)) * 2);
                asm volatile("ldmatrix.sync.aligned.m8n8.x4.shared.b16 {%0,%1,%2,%3}, [%4];\n"
                             : "=r"(a[im][0]), "=r"(a[im][1]), "=r"(a[im][2]), "=r"(a[im][3])
                             : "r"(addr));
            }
            uint32_t b[4][2];
#pragma unroll
            for (int in_ = 0; in_ < 4; in_++) {
                uint32_t addr = (uint32_t)__cvta_generic_to_shared(
                    sb + (wn * 32 + in_ * 8 + (lane & 7)) * 80 + (kk + (((lane >> 3) & 1) << 3)) * 2);
                asm volatile("ldmatrix.sync.aligned.m8n8.x2.shared.b16 {%0,%1}, [%2];\n"
                             : "=r"(b[in_][0]), "=r"(b[in_][1])
                             : "r"(addr));
            }
#pragma unroll
            for (int im = 0; im < 4; im++)
#pragma unroll
                for (int in_ = 0; in_ < 4; in_++)
                    asm volatile(
                        "mma.sync.aligned.m16n8k16.row.col.f32.bf16.bf16.f32 "
                        "{%0,%1,%2,%3}, {%4,%5,%6,%7}, {%8,%9}, {%0,%1,%2,%3};\n"
                        : "+f"(acc[im][in_][0]), "+f"(acc[im][in_][1]),
                          "+f"(acc[im][in_][2]), "+f"(acc[im][in_][3])
                        : "r"(a[im][0]), "r"(a[im][1]), "r"(a[im][2]), "r"(a[im][3]),
                          "r"(b[in_][0]), "r"(b[in_][1]));
        }
        __syncthreads();
    }

    // epilogue
    int r = lane >> 2;
    int cp2 = (lane & 3) * 2;
    int m_base = blockIdx.y * 128 + wm * 64;
    int n_base = blockIdx.x * 128 + wn * 32;

    if (EPI == 0) {
#pragma unroll
        for (int im = 0; im < 4; im++) {
            int m = m_base + im * 16 + r;
#pragma unroll
            for (int in_ = 0; in_ < 4; in_++) {
                int n = n_base + in_ * 8 + cp2;
                *(float2*)&g_H[(size_t)m * N_TOTAL + n] =
                    make_float2(acc[im][in_][0], acc[im][in_][1]);
                *(float2*)&g_H[(size_t)(m + 8) * N_TOTAL + n] =
                    make_float2(acc[im][in_][2], acc[im][in_][3]);
            }
        }
    } else {
#pragma unroll
        for (int im = 0; im < 4; im++) {
            int m = m_base + im * 16 + r;
            float gA = g_gate[m];
            float gB = g_gate[m + 8];
#pragma unroll
            for (int in_ = 0; in_ < 4; in_++) {
                int n = n_base + in_ * 8 + cp2;
                float2 xv0 = *(const float2*)&x[(size_t)m * DD + n];
                float2 xv1 = *(const float2*)&x[(size_t)(m + 8) * DD + n];
                float2 o0 = make_float2(xv0.x + gA * acc[im][in_][0],
                                        xv0.y + gA * acc[im][in_][1]);
                float2 o1 = make_float2(xv1.x + gB * acc[im][in_][2],
                                        xv1.y + gB * acc[im][in_][3]);
                *(float2*)&out[(size_t)m * DD + n] = o0;
                *(float2*)&out[(size_t)(m + 8) * DD + n] = o1;
            }
        }
    }
}

// ---------------- kernel 3: depthwise conv(k=3) + exact GELU -> bf16 ---------
__global__ __launch_bounds__(256) void k_conv() {
    int t = threadIdx.x;
    int row = blockIdx.x * 4 + (t >> 6);
    int c4 = t & 63;
    int s = row & (SS - 1);

    const float4* Hc = ((const float4*)g_H) + (size_t)row * (CC / 4);
    float4 z = make_float4(0.f, 0.f, 0.f, 0.f);
    float4 hm = (s > 0)      ? Hc[c4 - (CC / 4)] : z;
    float4 hc = Hc[c4];
    float4 hp = (s < SS - 1) ? Hc[c4 + (CC / 4)] : z;

    float4 w0 = ((const float4*)g_wc[0])[c4];
    float4 w1 = ((const float4*)g_wc[1])[c4];
    float4 w2 = ((const float4*)g_wc[2])[c4];

    float vx = gelu_exact(hm.x * w0.x + hc.x * w1.x + hp.x * w2.x);
    float vy = gelu_exact(hm.y * w0.y + hc.y * w1.y + hp.y * w2.y);
    float vz = gelu_exact(hm.z * w0.z + hc.z * w1.z + hp.z * w2.z);
    float vw = gelu_exact(hm.w * w0.w + hc.w * w1.w + hp.w * w2.w);

    __nv_bfloat162* G2 = ((__nv_bfloat162*)g_G) + (size_t)row * (CC / 2);
    G2[c4 * 2 + 0] = __floats2bfloat162_rn(vx, vy);
    G2[c4 * 2 + 1] = __floats2bfloat162_rn(vz, vw);
}

// ---------------- launch ------------------------------------------------------
extern "C" void kernel_launch(void* const* d_in, const int* in_sizes, int n_in,
                              void* d_out, int out_size) {
    const float* x      = (const float*)d_in[0];
    const float* gamma  = (const float*)d_in[1];
    const float* beta   = (const float*)d_in[2];
    const float* w_down = (const float*)d_in[3];
    const float* w_conv = (const float*)d_in[4];
    const float* w_up   = (const float*)d_in[5];
    const float* w_gate = (const float*)d_in[6];
    const float* b_gate = (const float*)d_in[7];
    float* out = (float*)d_out;

    cudaFuncSetAttribute(gemm_bf16<CC, DD, 0>,
                         cudaFuncAttributeMaxDynamicSharedMemorySize, GEMM_SMEM);
    cudaFuncSetAttribute(gemm_bf16<DD, CC, 1>,
                         cudaFuncAttributeMaxDynamicSharedMemorySize, GEMM_SMEM);

    k_cvt<<<4096, 256>>>(w_down, w_up, w_conv);
    k_ln<<<NROW, 256>>>((const float4*)x, gamma, beta, (const float4*)w_gate, b_gate);
    gemm_bf16<CC, DD, 0><<<dim3(CC / 128, NROW / 128), 256, GEMM_SMEM>>>(nullptr, nullptr);
    k_conv<<<NROW / 4, 256>>>();
    gemm_bf16<DD, CC, 1><<<dim3(DD / 128, NROW / 128), 256, GEMM_SMEM>>>(x, out);
}